// round 11
// baseline (speedup 1.0000x reference)
#include <cuda_runtime.h>
#include <math.h>

// ---------------------------------------------------------------------------
// PCasso predictive-coding relaxation, analytically collapsed:
//   so_final ~= x,  E = 0.5 * mean((x4v - x)^2)
// x4v = tanh(W4@x3v+b4), x3v = leaky(W3@x2v+b3), x2v = leaky(W2@x1+b2),
// x1 = leaky(W1[:,0]+b1).
//
// R11: ONE kernel, 784 blocks (single wave). The chain is warp-granular:
// global warp g computes one row (g<512: x2v row; 512<=g<1536: x3v row;
// 1536<=g<2320: x4v row) gated by flag counters — no grid barriers, no
// dedicated blocks. Every warp then runs the R5 copy loop; the energy
// combine at the end polls the x4v-done counter (long since satisfied).
// ---------------------------------------------------------------------------

#define N4_I     6422528          // 8192 * 784
#define NF4      1605632          // N4_I / 4
#define B_GRID   784              // 784*256*8 == NF4 exactly; single wave @6/SM
#define STRIDE4  200704           // 784*256; % 196 == 0 -> fixed column

__device__ float  g_x2v[512];
__device__ float  g_x3v[1024];
__device__ __align__(16) float g_x4v[784];
__device__ double g_part[B_GRID];
__device__ unsigned g_c2;         // x2v rows done (512)
__device__ unsigned g_c3;         // x3v rows done (1024)
__device__ unsigned g_c4;         // x4v rows done (784)
__device__ unsigned g_done;       // blocks finished (reset by final block)

__device__ __forceinline__ float leaky(float v) { return v >= 0.0f ? v : 0.2f * v; }

__device__ __forceinline__ float warp_sum(float v) {
    #pragma unroll
    for (int o = 16; o > 0; o >>= 1) v += __shfl_down_sync(0xffffffffu, v, o);
    return v;
}

// lane0 polls counter >= target, then whole warp fences.
__device__ __forceinline__ void wait_cnt(unsigned* ctr, unsigned target) {
    if ((threadIdx.x & 31) == 0) {
        volatile unsigned* vc = (volatile unsigned*)ctr;
        while (*vc < target) { __nanosleep(32); }
    }
    __syncwarp();
    __threadfence();
}

__global__ void __launch_bounds__(256, 6)
k_all(const float* __restrict__ x,
      const float* __restrict__ W1, const float* __restrict__ b1,
      const float* __restrict__ W2, const float* __restrict__ b2,
      const float* __restrict__ W3, const float* __restrict__ b3,
      const float* __restrict__ W4, const float* __restrict__ b4,
      float* __restrict__ out) {
    __shared__ double sd[256];
    __shared__ double s_w[8];
    __shared__ int    s_last;
    int t = threadIdx.x, warp = t >> 5, lane = t & 31;
    int b = blockIdx.x;
    int gwarp = b * 8 + warp;                 // 0..6271

    // =============== chain duty: one row per warp ===============
    if (gwarp < 512) {
        // x2v row r: dot(W2[r,:], x1) ; lane covers elems 8*lane..8*lane+7
        int r = gwarp;
        const float4* w = (const float4*)(W2 + r * 256);
        float s = 0.0f;
        #pragma unroll
        for (int m = 0; m < 2; m++) {
            int f4 = 2 * lane + m;            // float4 index 0..63
            float4 wv = __ldg(&w[f4]);
            int i0 = 4 * f4;
            float a0 = leaky(__ldg(&W1[i0  ]) + __ldg(&b1[i0  ]));
            float a1 = leaky(__ldg(&W1[i0+1]) + __ldg(&b1[i0+1]));
            float a2 = leaky(__ldg(&W1[i0+2]) + __ldg(&b1[i0+2]));
            float a3 = leaky(__ldg(&W1[i0+3]) + __ldg(&b1[i0+3]));
            s += wv.x * a0 + wv.y * a1 + wv.z * a2 + wv.w * a3;
        }
        s = warp_sum(s);
        if (lane == 0) {
            g_x2v[r] = leaky(s + __ldg(&b2[r]));
            __threadfence();
            atomicAdd(&g_c2, 1u);
        }
    } else if (gwarp < 1536) {
        // x3v row r: dot(W3[r,:], x2v) ; lane covers elems 16*lane..+15
        int r = gwarp - 512;
        wait_cnt(&g_c2, 512u);
        const float4* w  = (const float4*)(W3 + r * 512);
        const float4* xv = (const float4*)g_x2v;
        float s = 0.0f;
        #pragma unroll
        for (int m = 0; m < 4; m++) {
            int f4 = 4 * lane + m;            // 0..127
            float4 wv = __ldg(&w[f4]);
            float4 av = xv[f4];
            s += wv.x * av.x + wv.y * av.y + wv.z * av.z + wv.w * av.w;
        }
        s = warp_sum(s);
        if (lane == 0) {
            g_x3v[r] = leaky(s + __ldg(&b3[r]));
            __threadfence();
            atomicAdd(&g_c3, 1u);
        }
    } else if (gwarp < 2320) {
        // x4v row r: tanh(dot(W4[r,:], x3v) + b4) ; lane covers 32*lane..+31
        int r = gwarp - 1536;
        wait_cnt(&g_c3, 1024u);
        const float4* w  = (const float4*)(W4 + r * 1024);
        const float4* xv = (const float4*)g_x3v;
        float s = 0.0f;
        #pragma unroll
        for (int m = 0; m < 8; m++) {
            int f4 = 8 * lane + m;            // 0..255
            float4 wv = __ldg(&w[f4]);
            float4 av = xv[f4];
            s += wv.x * av.x + wv.y * av.y + wv.z * av.z + wv.w * av.w;
        }
        s = warp_sum(s);
        if (lane == 0) {
            g_x4v[r] = tanhf(s + __ldg(&b4[r]));
            __threadfence();
            atomicAdd(&g_c4, 1u);
        }
    }

    // =============== copy + moments (all warps; R5 loop) ===============
    const float4* x4p = (const float4*)x;
    float4* o4 = (float4*)out;
    int gtid = b * 256 + t;
    int c4 = gtid % 196;                      // fixed for all 8 iterations

    float4 sx = make_float4(0.f, 0.f, 0.f, 0.f);
    float sxx = 0.f;
    float lastw = 0.f;

    #pragma unroll
    for (int i = 0; i < 8; i++) {
        int k = gtid + i * STRIDE4;
        float4 xb = __ldg(&x4p[k]);

        float prev = __shfl_up_sync(0xffffffffu, xb.w, 1);
        if (lane == 0) prev = __ldg(&x[max(4*k - 1, 0)]);   // out[0]=E later
        o4[k] = make_float4(prev, xb.x, xb.y, xb.z);
        lastw = xb.w;

        sx.x += xb.x; sx.y += xb.y; sx.z += xb.z; sx.w += xb.w;
        sxx = fmaf(xb.x, xb.x, sxx);
        sxx = fmaf(xb.y, xb.y, sxx);
        sxx = fmaf(xb.z, xb.z, sxx);
        sxx = fmaf(xb.w, xb.w, sxx);
    }
    if (gtid == STRIDE4 - 1) out[N4_I] = lastw;   // tail (k = NF4-1)

    // =============== wait for x4v, combine energy ===============
    wait_cnt(&g_c4, 784u);

    const float4* x4v4 = (const float4*)g_x4v;
    float4 v = x4v4[c4];
    // closed-form per-thread energy: sum_c [8 v_c^2 - 2 v_c sx_c] + sxx
    float e = sxx;
    e = fmaf(v.x, fmaf(8.f, v.x, -2.f * sx.x), e);
    e = fmaf(v.y, fmaf(8.f, v.y, -2.f * sx.y), e);
    e = fmaf(v.z, fmaf(8.f, v.z, -2.f * sx.z), e);
    e = fmaf(v.w, fmaf(8.f, v.w, -2.f * sx.w), e);

    // deterministic block reduce
    e = warp_sum(e);
    if (lane == 0) s_w[warp] = (double)e;
    __syncthreads();
    if (t == 0) {
        double s = 0.0;
        #pragma unroll
        for (int i = 0; i < 8; i++) s += s_w[i];
        g_part[b] = s;
        __threadfence();
        unsigned r = atomicAdd(&g_done, 1u);
        s_last = (r == B_GRID - 1) ? 1 : 0;
    }
    __syncthreads();

    if (s_last) {                             // final block: global reduce
        __threadfence();
        double a = 0.0;
        for (int i = t; i < B_GRID; i += 256) a += g_part[i];
        sd[t] = a;
        __syncthreads();
        #pragma unroll
        for (int s = 128; s > 0; s >>= 1) {
            if (t < s) sd[t] += sd[t + s];
            __syncthreads();
        }
        if (t == 0) {
            out[0] = (float)(0.5 * sd[0] / 6422528.0);
            g_c2 = 0u; g_c3 = 0u; g_c4 = 0u;  // reset for next replay
            g_done = 0u;
        }
    }
}

extern "C" void kernel_launch(void* const* d_in, const int* in_sizes, int n_in,
                              void* d_out, int out_size) {
    const float* x    = (const float*)d_in[0];
    const float* W1   = (const float*)d_in[2];
    const float* b1   = (const float*)d_in[3];
    const float* W2   = (const float*)d_in[4];
    const float* b2   = (const float*)d_in[5];
    const float* W3   = (const float*)d_in[6];
    const float* b3   = (const float*)d_in[7];
    const float* W4   = (const float*)d_in[8];
    const float* b4   = (const float*)d_in[9];
    float* out = (float*)d_out;

    k_all<<<B_GRID, 256>>>(x, W1, b1, W2, b2, W3, b3, W4, b4, out);
}

// round 12
// speedup vs baseline: 1.9148x; 1.9148x over previous
#include <cuda_runtime.h>
#include <math.h>

// ---------------------------------------------------------------------------
// PCasso predictive-coding relaxation, analytically collapsed:
//   so_final ~= x,  E = 0.5 * mean((x4v - x)^2)
// x4v = tanh(W4@x3v+b4), x3v = leaky(W3@x2v+b3), x2v = leaky(W2@x1+b2),
// x1 = leaky(W1[:,0]+b1).
//
// R12 = R10 (single kernel, 64 chain blocks + 784 copy blocks, single wave)
// with POLLING-STORM SUPPRESSION: all spin-waits check once then back off
// with multi-microsecond nanosleeps. R11 proved that dense polling of one
// L2 line by many warps collapses DRAM throughput (493 GB/s); R7/R10's
// fused slowdown was the same mechanism in milder form.
// ---------------------------------------------------------------------------

#define N4_I     6422528          // 8192 * 784
#define NF4      1605632          // N4_I / 4
#define CHAIN_B  64
#define B_GRID   848              // 64 + 784; single wave at 6 blocks/SM (888)
#define STRIDE4  200704           // 784*256; % 196 == 0 -> fixed column

__device__ float  g_x2v[512];
__device__ float  g_x3v[1024];
__device__ __align__(16) float g_x4v[784];
__device__ double g_part[B_GRID];
__device__ unsigned g_bar1;       // reset by final block each launch
__device__ unsigned g_bar2;
__device__ unsigned g_chain_done;
__device__ unsigned g_done;

__device__ __forceinline__ float leaky(float v) { return v >= 0.0f ? v : 0.2f * v; }

__device__ __forceinline__ float warp_sum(float v) {
    #pragma unroll
    for (int o = 16; o > 0; o >>= 1) v += __shfl_down_sync(0xffffffffu, v, o);
    return v;
}

// Grid barrier among the CHAIN_B chain blocks (64 pollers, gentle backoff).
__device__ __forceinline__ void grid_bar(unsigned* ctr) {
    __syncthreads();
    if (threadIdx.x == 0) {
        __threadfence();
        atomicAdd(ctr, 1u);
        volatile unsigned* vc = (volatile unsigned*)ctr;
        while (*vc < CHAIN_B) { __nanosleep(512); }
    }
    __syncthreads();
    __threadfence();
}

__global__ void __launch_bounds__(256, 6)
k_fused(const float* __restrict__ x,
        const float* __restrict__ W1, const float* __restrict__ b1,
        const float* __restrict__ W2, const float* __restrict__ b2,
        const float* __restrict__ W3, const float* __restrict__ b3,
        const float* __restrict__ W4, const float* __restrict__ b4,
        float* __restrict__ out) {
    __shared__ float  sh[1024];
    __shared__ double sd[256];
    __shared__ double s_w[8];
    __shared__ int    s_last;
    int t = threadIdx.x, warp = t >> 5, lane = t & 31;
    int b = blockIdx.x;

    float4 sx = make_float4(0.f, 0.f, 0.f, 0.f);
    float sxx = 0.f;
    int c4 = 0;

    if (b < CHAIN_B) {
        // ================= chain (blocks 0..63), copy-free =================
        // stage A: x1 (shared) -> x2v ; 512 rows = warp*64 + b
        sh[t] = leaky(W1[t] + b1[t]);
        __syncthreads();
        {
            int row = warp * 64 + b;
            const float4* w = (const float4*)(W2 + row * 256);
            float s = 0.0f;
            #pragma unroll
            for (int j = lane; j < 64; j += 32) {
                float4 wv = w[j];
                s += wv.x * sh[4*j] + wv.y * sh[4*j+1] + wv.z * sh[4*j+2] + wv.w * sh[4*j+3];
            }
            s = warp_sum(s);
            if (lane == 0) g_x2v[row] = leaky(s + b2[row]);
        }
        grid_bar(&g_bar1);

        // stage B: x2v -> x3v ; 1024 rows, two strided passes
        __syncthreads();
        sh[t] = g_x2v[t];
        sh[t + 256] = g_x2v[t + 256];
        __syncthreads();
        for (int row = warp * 64 + b; row < 1024; row += 512) {
            const float4* w = (const float4*)(W3 + row * 512);
            float s = 0.0f;
            #pragma unroll
            for (int j = lane; j < 128; j += 32) {
                float4 wv = w[j];
                s += wv.x * sh[4*j] + wv.y * sh[4*j+1] + wv.z * sh[4*j+2] + wv.w * sh[4*j+3];
            }
            s = warp_sum(s);
            if (lane == 0) g_x3v[row] = leaky(s + b3[row]);
        }
        grid_bar(&g_bar2);

        // stage C: x3v -> x4v ; 784 rows
        __syncthreads();
        #pragma unroll
        for (int kk = 0; kk < 4; kk++) sh[t + 256 * kk] = g_x3v[t + 256 * kk];
        __syncthreads();
        for (int row = warp * 64 + b; row < 784; row += 512) {
            const float4* w = (const float4*)(W4 + row * 1024);
            float s = 0.0f;
            #pragma unroll
            for (int j = lane; j < 256; j += 32) {
                float4 wv = w[j];
                s += wv.x * sh[4*j] + wv.y * sh[4*j+1] + wv.z * sh[4*j+2] + wv.w * sh[4*j+3];
            }
            s = warp_sum(s);
            if (lane == 0) g_x4v[row] = tanhf(s + b4[row]);
        }
        __threadfence();
        __syncthreads();
        if (t == 0) atomicAdd(&g_chain_done, 1u);
    } else {
        // ================= copy (blocks 64..847): R5 loop ==================
        const float4* x4p = (const float4*)x;
        float4* o4 = (float4*)out;
        int gtid = (b - CHAIN_B) * 256 + t;
        c4 = gtid % 196;                     // fixed for all 8 iterations
        float lastw = 0.f;

        #pragma unroll
        for (int i = 0; i < 8; i++) {
            int k = gtid + i * STRIDE4;
            float4 xb = __ldg(&x4p[k]);

            float prev = __shfl_up_sync(0xffffffffu, xb.w, 1);
            if (lane == 0) prev = __ldg(&x[max(4*k - 1, 0)]);   // out[0]=E later
            o4[k] = make_float4(prev, xb.x, xb.y, xb.z);
            lastw = xb.w;

            sx.x += xb.x; sx.y += xb.y; sx.z += xb.z; sx.w += xb.w;
            sxx = fmaf(xb.x, xb.x, sxx);
            sxx = fmaf(xb.y, xb.y, sxx);
            sxx = fmaf(xb.z, xb.z, sxx);
            sxx = fmaf(xb.w, xb.w, sxx);
        }
        if (gtid == STRIDE4 - 1) out[N4_I] = lastw;   // tail (k = NF4-1)
    }

    // ===== wait for chain: check once (common case passes), huge backoff ====
    if (t == 0) {
        volatile unsigned* vc = (volatile unsigned*)&g_chain_done;
        while (*vc < CHAIN_B) { __nanosleep(8192); }
    }
    __syncthreads();
    __threadfence();

    float e = 0.0f;
    if (b >= CHAIN_B) {
        const float4* x4v4 = (const float4*)g_x4v;
        float4 v = x4v4[c4];
        // closed-form per-thread energy: sum_c [8 v_c^2 - 2 v_c sx_c] + sxx
        e = sxx;
        e = fmaf(v.x, fmaf(8.f, v.x, -2.f * sx.x), e);
        e = fmaf(v.y, fmaf(8.f, v.y, -2.f * sx.y), e);
        e = fmaf(v.z, fmaf(8.f, v.z, -2.f * sx.z), e);
        e = fmaf(v.w, fmaf(8.f, v.w, -2.f * sx.w), e);
    }

    // deterministic block reduce
    e = warp_sum(e);
    if (lane == 0) s_w[warp] = (double)e;
    __syncthreads();
    if (t == 0) {
        double s = 0.0;
        #pragma unroll
        for (int i = 0; i < 8; i++) s += s_w[i];
        g_part[b] = s;
        __threadfence();
        unsigned r = atomicAdd(&g_done, 1u);
        s_last = (r == B_GRID - 1) ? 1 : 0;
    }
    __syncthreads();

    if (s_last) {                         // final block: global reduce
        __threadfence();
        double a = 0.0;
        for (int i = t; i < B_GRID; i += 256) a += g_part[i];
        sd[t] = a;
        __syncthreads();
        #pragma unroll
        for (int s = 128; s > 0; s >>= 1) {
            if (t < s) sd[t] += sd[t + s];
            __syncthreads();
        }
        if (t == 0) {
            out[0] = (float)(0.5 * sd[0] / 6422528.0);
            g_bar1 = 0u; g_bar2 = 0u;     // reset for next replay
            g_chain_done = 0u;
            g_done = 0u;
        }
    }
}

extern "C" void kernel_launch(void* const* d_in, const int* in_sizes, int n_in,
                              void* d_out, int out_size) {
    const float* x    = (const float*)d_in[0];
    const float* W1   = (const float*)d_in[2];
    const float* b1   = (const float*)d_in[3];
    const float* W2   = (const float*)d_in[4];
    const float* b2   = (const float*)d_in[5];
    const float* W3   = (const float*)d_in[6];
    const float* b3   = (const float*)d_in[7];
    const float* W4   = (const float*)d_in[8];
    const float* b4   = (const float*)d_in[9];
    float* out = (float*)d_out;

    k_fused<<<B_GRID, 256>>>(x, W1, b1, W2, b2, W3, b3, W4, b4, out);
}

// round 14
// speedup vs baseline: 3.3684x; 1.7592x over previous
#include <cuda_runtime.h>
#include <math.h>

// ---------------------------------------------------------------------------
// PCasso predictive-coding relaxation, analytically collapsed:
//   so_final ~= x,  E = 0.5 * mean((x4v - x)^2)
// x4v = tanh(W4@x3v+b4), x3v = leaky(W3@x2v+b3), x2v = leaky(W2@x1+b2),
// x1 = leaky(W1[:,0]+b1).
//
// R14: k_main uses 256-bit (32B) global accesses — the only width on which
// sm_100a accepts L2 eviction hints, and it halves LDG/STG/SHFL counts:
//   x   : ld.global.nc.L2::evict_last.v4.b64   (retain in L2 across replays)
//   out : st.global.L2::evict_first.v4.b64     (stream, don't displace x)
// 4 units of 8 floats per thread; stride 200704 units % 98 == 0 -> fixed
// x4v column-pair per thread; closed-form energy 4v^2 - 2 v sx + sxx.
// ---------------------------------------------------------------------------

#define N4_I     6422528          // 8192 * 784
#define NF8      802816           // N4_I / 8
#define MBLK     784              // 784*256*4 == NF8 exactly
#define STRIDE8  200704           // 784*256; % 98 == 0 -> fixed column-pair
#define CHAIN_B  128

__device__ float  g_x2v[512];
__device__ float  g_x3v[1024];
__device__ __align__(16) float g_x4v[784];
__device__ double g_part[MBLK];
__device__ unsigned g_bar1;       // reset by k_main for next replay
__device__ unsigned g_bar2;
__device__ unsigned g_done;       // reset by the last k_main block

__device__ __forceinline__ float leaky(float v) { return v >= 0.0f ? v : 0.2f * v; }

__device__ __forceinline__ float warp_sum(float v) {
    #pragma unroll
    for (int o = 16; o > 0; o >>= 1) v += __shfl_down_sync(0xffffffffu, v, o);
    return v;
}

// 32B load of x, L2 evict_last (retained across graph replays).
__device__ __forceinline__ void ldg256_keep(const float* p, float4& a, float4& b) {
    unsigned long long r0, r1, r2, r3;
    asm volatile("ld.global.nc.L2::evict_last.v4.b64 {%0,%1,%2,%3}, [%4];"
                 : "=l"(r0), "=l"(r1), "=l"(r2), "=l"(r3) : "l"(p));
    a.x = __uint_as_float((unsigned)r0);  a.y = __uint_as_float((unsigned)(r0 >> 32));
    a.z = __uint_as_float((unsigned)r1);  a.w = __uint_as_float((unsigned)(r1 >> 32));
    b.x = __uint_as_float((unsigned)r2);  b.y = __uint_as_float((unsigned)(r2 >> 32));
    b.z = __uint_as_float((unsigned)r3);  b.w = __uint_as_float((unsigned)(r3 >> 32));
}

// 32B store of out, L2 evict_first (streaming).
__device__ __forceinline__ void stg256_stream(float* p, float4 a, float4 b) {
    unsigned long long r0 = ((unsigned long long)__float_as_uint(a.y) << 32) | __float_as_uint(a.x);
    unsigned long long r1 = ((unsigned long long)__float_as_uint(a.w) << 32) | __float_as_uint(a.z);
    unsigned long long r2 = ((unsigned long long)__float_as_uint(b.y) << 32) | __float_as_uint(b.x);
    unsigned long long r3 = ((unsigned long long)__float_as_uint(b.w) << 32) | __float_as_uint(b.z);
    asm volatile("st.global.L2::evict_first.v4.b64 [%0], {%1,%2,%3,%4};"
                 :: "l"(p), "l"(r0), "l"(r1), "l"(r2), "l"(r3) : "memory");
}

__device__ __forceinline__ void grid_bar(unsigned* ctr) {
    __syncthreads();
    if (threadIdx.x == 0) {
        __threadfence();
        atomicAdd(ctr, 1u);
        volatile unsigned* vc = (volatile unsigned*)ctr;
        while (*vc < CHAIN_B) { __nanosleep(64); }
    }
    __syncthreads();
    __threadfence();
}

// Fused x1 -> x2v -> x3v -> x4v with software grid barriers (128 blocks).
__global__ void __launch_bounds__(256)
k_chain(const float* __restrict__ W1, const float* __restrict__ b1,
        const float* __restrict__ W2, const float* __restrict__ b2,
        const float* __restrict__ W3, const float* __restrict__ b3,
        const float* __restrict__ W4, const float* __restrict__ b4) {
    __shared__ float sh[1024];
    int t = threadIdx.x, warp = t >> 5, lane = t & 31;

    sh[t] = leaky(W1[t] + b1[t]);
    __syncthreads();
    if (warp < 4) {
        int row = warp * 128 + blockIdx.x;
        const float4* w = (const float4*)(W2 + row * 256);
        float s = 0.0f;
        #pragma unroll
        for (int j = lane; j < 64; j += 32) {
            float4 wv = w[j];
            s += wv.x * sh[4*j] + wv.y * sh[4*j+1] + wv.z * sh[4*j+2] + wv.w * sh[4*j+3];
        }
        s = warp_sum(s);
        if (lane == 0) g_x2v[row] = leaky(s + b2[row]);
    }
    grid_bar(&g_bar1);

    __syncthreads();
    sh[t] = g_x2v[t];
    sh[t + 256] = g_x2v[t + 256];
    __syncthreads();
    {
        int row = warp * 128 + blockIdx.x;
        const float4* w = (const float4*)(W3 + row * 512);
        float s = 0.0f;
        #pragma unroll
        for (int j = lane; j < 128; j += 32) {
            float4 wv = w[j];
            s += wv.x * sh[4*j] + wv.y * sh[4*j+1] + wv.z * sh[4*j+2] + wv.w * sh[4*j+3];
        }
        s = warp_sum(s);
        if (lane == 0) g_x3v[row] = leaky(s + b3[row]);
    }
    grid_bar(&g_bar2);

    __syncthreads();
    #pragma unroll
    for (int kk = 0; kk < 4; kk++) sh[t + 256 * kk] = g_x3v[t + 256 * kk];
    __syncthreads();
    {
        int row = warp * 128 + blockIdx.x;
        if (row < 784) {
            const float4* w = (const float4*)(W4 + row * 1024);
            float s = 0.0f;
            #pragma unroll
            for (int j = lane; j < 256; j += 32) {
                float4 wv = w[j];
                s += wv.x * sh[4*j] + wv.y * sh[4*j+1] + wv.z * sh[4*j+2] + wv.w * sh[4*j+3];
            }
            s = warp_sum(s);
            if (lane == 0) g_x4v[row] = tanhf(s + b4[row]);
        }
    }
}

// 4 x 32B units per thread, fixed x4v column-pair, fully unrolled.
// out8[k] = {x[8k-1], x[8k..8k+6]} via shfl; fused deterministic reduce.
__global__ void __launch_bounds__(256)
k_main(const float* __restrict__ x, float* __restrict__ out) {
    __shared__ double s_w[8];
    __shared__ double sd[256];
    __shared__ int    s_last;
    int t = threadIdx.x, warp = t >> 5, lane = t & 31;

    if (blockIdx.x == 0 && t == 0) { g_bar1 = 0u; g_bar2 = 0u; }  // replay reset

    const float4* x4v4 = (const float4*)g_x4v;   // 196 float4 columns
    int gtid = blockIdx.x * 256 + t;
    int c8 = gtid % 98;                          // fixed unit-column (8 floats)

    float4 sxa = make_float4(0.f, 0.f, 0.f, 0.f);
    float4 sxb = make_float4(0.f, 0.f, 0.f, 0.f);
    float sxx = 0.f;
    float lastw = 0.f;

    #pragma unroll
    for (int i = 0; i < 4; i++) {
        int k = gtid + i * STRIDE8;
        float4 a, b;
        ldg256_keep(x + 8 * (size_t)k, a, b);

        float prev = __shfl_up_sync(0xffffffffu, b.w, 1);
        if (lane == 0) prev = __ldg(&x[max(8*k - 1, 0)]);   // out[0]=E later
        stg256_stream(out + 8 * (size_t)k,
                      make_float4(prev, a.x, a.y, a.z),
                      make_float4(a.w, b.x, b.y, b.z));
        lastw = b.w;

        sxa.x += a.x; sxa.y += a.y; sxa.z += a.z; sxa.w += a.w;
        sxb.x += b.x; sxb.y += b.y; sxb.z += b.z; sxb.w += b.w;
        sxx = fmaf(a.x, a.x, sxx); sxx = fmaf(a.y, a.y, sxx);
        sxx = fmaf(a.z, a.z, sxx); sxx = fmaf(a.w, a.w, sxx);
        sxx = fmaf(b.x, b.x, sxx); sxx = fmaf(b.y, b.y, sxx);
        sxx = fmaf(b.z, b.z, sxx); sxx = fmaf(b.w, b.w, sxx);
    }
    if (gtid == STRIDE8 - 1) out[N4_I] = lastw;  // tail element (k = NF8-1)

    // energy combine (x4v ready by kernel ordering)
    float4 va = __ldg(&x4v4[2 * c8]);
    float4 vb = __ldg(&x4v4[2 * c8 + 1]);
    float e = sxx;
    e = fmaf(va.x, fmaf(4.f, va.x, -2.f * sxa.x), e);
    e = fmaf(va.y, fmaf(4.f, va.y, -2.f * sxa.y), e);
    e = fmaf(va.z, fmaf(4.f, va.z, -2.f * sxa.z), e);
    e = fmaf(va.w, fmaf(4.f, va.w, -2.f * sxa.w), e);
    e = fmaf(vb.x, fmaf(4.f, vb.x, -2.f * sxb.x), e);
    e = fmaf(vb.y, fmaf(4.f, vb.y, -2.f * sxb.y), e);
    e = fmaf(vb.z, fmaf(4.f, vb.z, -2.f * sxb.z), e);
    e = fmaf(vb.w, fmaf(4.f, vb.w, -2.f * sxb.w), e);

    // deterministic block reduce
    e = warp_sum(e);
    if (lane == 0) s_w[warp] = (double)e;
    __syncthreads();
    if (t == 0) {
        double s = 0.0;
        #pragma unroll
        for (int i = 0; i < 8; i++) s += s_w[i];
        g_part[blockIdx.x] = s;
        __threadfence();
        unsigned r = atomicAdd(&g_done, 1u);
        s_last = (r == MBLK - 1) ? 1 : 0;
    }
    __syncthreads();

    if (s_last) {                                // last block: final reduce
        __threadfence();
        double a = 0.0;
        for (int i = t; i < MBLK; i += 256) a += g_part[i];
        sd[t] = a;
        __syncthreads();
        #pragma unroll
        for (int s = 128; s > 0; s >>= 1) {
            if (t < s) sd[t] += sd[t + s];
            __syncthreads();
        }
        if (t == 0) {
            out[0] = (float)(0.5 * sd[0] / 6422528.0);
            g_done = 0u;                         // reset for next replay
        }
    }
}

extern "C" void kernel_launch(void* const* d_in, const int* in_sizes, int n_in,
                              void* d_out, int out_size) {
    const float* x    = (const float*)d_in[0];
    const float* W1   = (const float*)d_in[2];
    const float* b1   = (const float*)d_in[3];
    const float* W2   = (const float*)d_in[4];
    const float* b2   = (const float*)d_in[5];
    const float* W3   = (const float*)d_in[6];
    const float* b3   = (const float*)d_in[7];
    const float* W4   = (const float*)d_in[8];
    const float* b4   = (const float*)d_in[9];
    float* out = (float*)d_out;

    k_chain<<<CHAIN_B, 256>>>(W1, b1, W2, b2, W3, b3, W4, b4);
    k_main<<<MBLK, 256>>>(x, out);
}